// round 10
// baseline (speedup 1.0000x reference)
#include <cuda_runtime.h>
#include <cstdint>

// Problem constants
#define B_  4
#define S_  2048
#define E_  512
#define Q_  8
#define F_  2048
#define M_  (B_ * S_)

// Tiling: CTA 64x128, warp tile 32x32, 8 warps (2m x 4n), 3 CTAs/SM target
#define BM 64
#define BN 128
#define BK 32
#define NTH 256
#define NCHUNK (F_ / BK)      // 64
#define PADA 36               // hs row stride (floats): conflict-free A frags

// SMEM (floats): hs double-buffered + B chunk double-buffered (lane-major)
#define HS_F    (BM * PADA)           // 2304
#define BCH_F   4096                  // 16 KB per chunk (BK x BN floats)
#define SMEM_TOTAL_BYTES ((2 * HS_F + 2 * BCH_F) * 4)   // 51200 B

// W2 permuted into lane-major fragment order, tf32-pre-rounded:
//   [c (64)][n0blk (4)][ float4s: ((wnb*4 + ks)*2 + f)*32 + lane ][elem]
//   for element (k, n):
//     ks = (k&31)>>3, t = k&3, rh = (k&7)>>2
//     wnb = (n&127)>>5, g = n&7, nt = (n&31)>>3
//     f = rh, elem = nt, lane = g*4 + t
__device__ float g_W2P[(size_t)F_ * E_];

// ---------------- helpers ----------------
__device__ __forceinline__ uint32_t smem_u32(const void* p) {
    uint32_t a;
    asm("{ .reg .u64 t; cvta.to.shared.u64 t, %1; cvt.u32.u64 %0, t; }" : "=r"(a) : "l"(p));
    return a;
}
__device__ __forceinline__ float to_tf32(float f) {
    uint32_t r;
    asm("cvt.rna.tf32.f32 %0, %1;" : "=r"(r) : "f"(f));
    return __uint_as_float(r);
}
__device__ __forceinline__ void cp16(uint32_t dst, const void* src) {
    asm volatile("cp.async.cg.shared.global [%0], [%1], 16;" :: "r"(dst), "l"(src));
}
#define CP_COMMIT() asm volatile("cp.async.commit_group;" ::: "memory")
#define CP_WAIT0()  asm volatile("cp.async.wait_group 0;" ::: "memory")

// D(16x8,f32) += A(16x8,tf32 row) * B(8x8,tf32 col)
__device__ __forceinline__ void mma8(float* d, const uint32_t* a, const uint32_t* b) {
    asm volatile(
        "mma.sync.aligned.m16n8k8.row.col.f32.tf32.tf32.f32 "
        "{%0,%1,%2,%3}, {%4,%5,%6,%7}, {%8,%9}, {%0,%1,%2,%3};"
        : "+f"(d[0]), "+f"(d[1]), "+f"(d[2]), "+f"(d[3])
        : "r"(a[0]), "r"(a[1]), "r"(a[2]), "r"(a[3]), "r"(b[0]), "r"(b[1]));
}

// ---------------- prepass: permute + tf32-round W2 into g_W2P ----------------
__global__ void w2_permute_kernel(const float* __restrict__ W2) {
    const int idx = blockIdx.x * 256 + threadIdx.x;     // 0 .. F_*E_-1
    const int k = idx >> 9;            // / E_
    const int n = idx & (E_ - 1);

    const int c   = k >> 5;            // chunk
    const int kk  = k & 31;
    const int ks  = kk >> 3;
    const int r8  = kk & 7;
    const int t   = r8 & 3;
    const int rh  = r8 >> 2;           // k offset +0 or +4

    const int n0blk = n >> 7;          // BN=128 block (0..3)
    const int n128  = n & 127;
    const int wnb   = n128 >> 5;       // warp n-block (0..3)
    const int n32   = n128 & 31;
    const int g     = n32 & 7;
    const int nt    = n32 >> 3;        // 0..3

    const int f    = rh;
    const int elem = nt;
    const int lane = g * 4 + t;

    const size_t f4idx = (size_t)(((wnb * 4 + ks) * 2 + f) * 32 + lane);
    const size_t dst = ((size_t)c * 4 + n0blk) * BCH_F + f4idx * 4 + elem;
    g_W2P[dst] = to_tf32(W2[(size_t)k * E_ + n]);
}

// ---------------- fused kernel ----------------
// out[m,e] = sum_k relu(b1[k] + sum_q cos(th[q])cos(x[m,q]) W1[q,k]) * W2[k,e] + b2[e]
__global__ __launch_bounds__(NTH, 3)
void ffq_mma_kernel(const float* __restrict__ x,
                    const float* __restrict__ theta,
                    const float* __restrict__ W1,
                    const float* __restrict__ b1,
                    const float* __restrict__ b2,
                    float* __restrict__ out) {
    extern __shared__ float smf[];
    float* hsbuf = smf;                    // [2][BM][PADA]
    float* bbuf  = smf + 2 * HS_F;         // [2][BCH_F]
    const uint32_t sb_b = smem_u32(bbuf);

    const int tid = threadIdx.x;
    const int w   = tid >> 5;
    const int l   = tid & 31;
    const int m0  = blockIdx.x * BM;
    const int n0  = blockIdx.y * BN;

    // warp tile: 2 (m) x 4 (n); WM=32, WN=32
    const int wm  = (w & 1) * 32;
    const int wn  = (w >> 1) * 32;
    const int wnb = w >> 1;

    // h roles
    const int hm = tid & 63;
    const int kq = tid >> 6;

    // fragment lane decomposition
    const int g = l >> 2;
    const int t = l & 3;

    // gmem base for this CTA's permuted B chunks (stride 4*BCH_F per chunk)
    const float* w2pc = g_W2P + (size_t)blockIdx.y * BCH_F;

    // ---- z registers ----
    float zreg[Q_];
    {
        const float4 x0 = *(const float4*)(x + (size_t)(m0 + hm) * E_);
        const float4 x1 = *(const float4*)(x + (size_t)(m0 + hm) * E_ + 4);
        zreg[0] = cosf(theta[0]) * cosf(x0.x);
        zreg[1] = cosf(theta[1]) * cosf(x0.y);
        zreg[2] = cosf(theta[2]) * cosf(x0.z);
        zreg[3] = cosf(theta[3]) * cosf(x0.w);
        zreg[4] = cosf(theta[4]) * cosf(x1.x);
        zreg[5] = cosf(theta[5]) * cosf(x1.y);
        zreg[6] = cosf(theta[6]) * cosf(x1.z);
        zreg[7] = cosf(theta[7]) * cosf(x1.w);
    }

    // ---- prologue: cp.async chunk 0 -> buf0 (linear, coalesced; 1024 float4) ----
    {
        const float* src = w2pc;           // c = 0
        #pragma unroll
        for (int i = 0; i < 4; i++)
            cp16(sb_b + (uint32_t)(i * 256 + tid) * 16u,
                 src + (size_t)(i * 256 + tid) * 4);
        CP_COMMIT();
    }
    // ---- compute h(0) -> hs[0] ----
    {
        float* hs0 = hsbuf;
        #pragma unroll
        for (int c2 = 0; c2 < 2; c2++) {
            const int kk = kq * 8 + c2 * 4;
            const float4 b1v = *(const float4*)(b1 + kk);
            float h0 = b1v.x, h1 = b1v.y, h2 = b1v.z, h3 = b1v.w;
            #pragma unroll
            for (int q = 0; q < Q_; q++) {
                const float4 wv = *(const float4*)(W1 + (size_t)q * F_ + kk);
                h0 = fmaf(zreg[q], wv.x, h0);
                h1 = fmaf(zreg[q], wv.y, h1);
                h2 = fmaf(zreg[q], wv.z, h2);
                h3 = fmaf(zreg[q], wv.w, h3);
            }
            float4 o;
            o.x = to_tf32(fmaxf(h0, 0.0f));
            o.y = to_tf32(fmaxf(h1, 0.0f));
            o.z = to_tf32(fmaxf(h2, 0.0f));
            o.w = to_tf32(fmaxf(h3, 0.0f));
            *(float4*)(hs0 + hm * PADA + kk) = o;
        }
    }

    float acc[2][4][4];
    #pragma unroll
    for (int mt = 0; mt < 2; mt++)
        #pragma unroll
        for (int nt = 0; nt < 4; nt++)
            #pragma unroll
            for (int v = 0; v < 4; v++) acc[mt][nt][v] = 0.0f;

    for (int c = 0; c < NCHUNK; c++) {
        const int rb = c & 1;

        CP_WAIT0();
        __syncthreads();     // cp(c) + h(c) visible; prior buffer reads done

        // ---- cp.async chunk c+1 into other B buffer ----
        if (c + 1 < NCHUNK) {
            const uint32_t dstb = sb_b + (uint32_t)(rb ^ 1) * (BCH_F * 4u);
            const float* src = w2pc + (size_t)(c + 1) * 4 * BCH_F;
            #pragma unroll
            for (int i = 0; i < 4; i++)
                cp16(dstb + (uint32_t)(i * 256 + tid) * 16u,
                     src + (size_t)(i * 256 + tid) * 4);
            CP_COMMIT();
        }

        // ---- h(c+1) into hs[(c+1)&1] (overlaps MMA(c) below) ----
        if (c + 1 < NCHUNK) {
            const int kc1 = (c + 1) * BK;
            float* hsn = hsbuf + (rb ^ 1) * HS_F;
            #pragma unroll
            for (int c2 = 0; c2 < 2; c2++) {
                const int kk = kq * 8 + c2 * 4;
                const float4 b1v = *(const float4*)(b1 + kc1 + kk);
                float h0 = b1v.x, h1 = b1v.y, h2 = b1v.z, h3 = b1v.w;
                #pragma unroll
                for (int q = 0; q < Q_; q++) {
                    const float4 wv = *(const float4*)(W1 + (size_t)q * F_ + kc1 + kk);
                    h0 = fmaf(zreg[q], wv.x, h0);
                    h1 = fmaf(zreg[q], wv.y, h1);
                    h2 = fmaf(zreg[q], wv.z, h2);
                    h3 = fmaf(zreg[q], wv.w, h3);
                }
                float4 o;
                o.x = to_tf32(fmaxf(h0, 0.0f));
                o.y = to_tf32(fmaxf(h1, 0.0f));
                o.z = to_tf32(fmaxf(h2, 0.0f));
                o.w = to_tf32(fmaxf(h3, 0.0f));
                *(float4*)(hsn + hm * PADA + kk) = o;
            }
        }

        // ---- MMA(c) ----
        const float* hsc = hsbuf + rb * HS_F;
        const float4* bch = (const float4*)(bbuf + rb * BCH_F);
        #pragma unroll
        for (int ks = 0; ks < 4; ks++) {
            const int kb = ks * 8;
            // A fragments (scalar LDS, conflict-free via PADA)
            uint32_t a[2][4];
            #pragma unroll
            for (int mt = 0; mt < 2; mt++) {
                const int r0 = wm + mt * 16 + g;
                const float* base = hsc + r0 * PADA + kb + t;
                a[mt][0] = __float_as_uint(base[0]);
                a[mt][1] = __float_as_uint(base[8 * PADA]);
                a[mt][2] = __float_as_uint(base[4]);
                a[mt][3] = __float_as_uint(base[8 * PADA + 4]);
            }
            // B fragments: 2x LDS.128, lane-major -> static names, conflict-free
            const float4* blk = bch + (size_t)((wnb * 4 + ks) * 2) * 32 + l;
            const float4 lg0 = blk[0];        // rh=0: nt 0..3
            const float4 lg1 = blk[32];       // rh=1: nt 0..3
            uint32_t bf[4][2];
            bf[0][0] = __float_as_uint(lg0.x); bf[1][0] = __float_as_uint(lg0.y);
            bf[2][0] = __float_as_uint(lg0.z); bf[3][0] = __float_as_uint(lg0.w);
            bf[0][1] = __float_as_uint(lg1.x); bf[1][1] = __float_as_uint(lg1.y);
            bf[2][1] = __float_as_uint(lg1.z); bf[3][1] = __float_as_uint(lg1.w);

            #pragma unroll
            for (int mt = 0; mt < 2; mt++)
                #pragma unroll
                for (int nt = 0; nt < 4; nt++)
                    mma8(acc[mt][nt], a[mt], bf[nt]);
        }
    }

    // ---- epilogue: add b2, store ----
    {
        #pragma unroll
        for (int nt = 0; nt < 4; nt++) {
            const int col = n0 + wn + nt * 8 + t * 2;
            const float2 bb = *(const float2*)(b2 + col);
            #pragma unroll
            for (int mt = 0; mt < 2; mt++) {
                const int r0 = m0 + wm + mt * 16 + g;
                float2 v0, v1;
                v0.x = acc[mt][nt][0] + bb.x;
                v0.y = acc[mt][nt][1] + bb.y;
                v1.x = acc[mt][nt][2] + bb.x;
                v1.y = acc[mt][nt][3] + bb.y;
                *(float2*)(out + (size_t)r0 * E_ + col)       = v0;
                *(float2*)(out + (size_t)(r0 + 8) * E_ + col) = v1;
            }
        }
    }
}

extern "C" void kernel_launch(void* const* d_in, const int* in_sizes, int n_in,
                              void* d_out, int out_size) {
    // Identify inputs by element count (order-proof; all sizes distinct)
    const float *x = nullptr, *theta = nullptr, *W1 = nullptr,
                *b1 = nullptr, *W2 = nullptr, *b2 = nullptr;
    for (int i = 0; i < n_in; i++) {
        switch (in_sizes[i]) {
            case B_ * S_ * E_: x     = (const float*)d_in[i]; break;
            case F_ * E_:      W2    = (const float*)d_in[i]; break;
            case Q_ * F_:      W1    = (const float*)d_in[i]; break;
            case F_:           b1    = (const float*)d_in[i]; break;
            case E_:           b2    = (const float*)d_in[i]; break;
            case Q_:           theta = (const float*)d_in[i]; break;
            default: break;
        }
    }
    float* out = (float*)d_out;

    cudaFuncSetAttribute(ffq_mma_kernel,
                         cudaFuncAttributeMaxDynamicSharedMemorySize,
                         SMEM_TOTAL_BYTES);

    // prepass: permute + tf32-round W2 into lane-major fragment order
    w2_permute_kernel<<<(F_ * E_) / 256, 256>>>(W2);

    dim3 grid(M_ / BM, E_ / BN);   // 128 x 4 = 512 CTAs, ~3 CTAs/SM
    ffq_mma_kernel<<<grid, NTH, SMEM_TOTAL_BYTES>>>(x, theta, W1, b1, b2, out);
}

// round 11
// speedup vs baseline: 1.6203x; 1.6203x over previous
#include <cuda_runtime.h>
#include <cstdint>

// Problem constants
#define B_  4
#define S_  2048
#define E_  512
#define Q_  8
#define F_  2048
#define M_  (B_ * S_)

// Tiling (round-9 best config)
#define BM 64
#define BN 256
#define BK 32
#define NTH 256
#define NCHUNK (F_ / BK)      // 64
#define PADA 36               // hs row stride (floats): conflict-free A frags

// SMEM (floats): hs double-buffered + B chunk double-buffered (lane-major, 8192 f each)
#define HS_F    (BM * PADA)           // 2304
#define BCH_F   8192                  // 32 KB per chunk, fragment/lane-ordered
#define SMEM_TOTAL_BYTES ((2 * HS_F + 2 * BCH_F) * 4)   // 83968 B

// W2 permuted into lane-major fragment order, tf32-pre-rounded:
//   [c (64)][n0blk (2)][ float4s: ((wnb*4 + ks)*4 + f)*32 + lane ][elem]
//   for element (k, n):
//     ks = (k&31)>>3, t = k&3, rh = (k&7)>>2
//     wnb = (n&255)>>6, g = n&7, nt = (n&63)>>3
//     f = rh*2 + (nt>>2), elem = nt&3, lane = g*4 + t
__device__ float g_W2P[(size_t)F_ * E_];

// ---------------- helpers ----------------
__device__ __forceinline__ uint32_t smem_u32(const void* p) {
    uint32_t a;
    asm("{ .reg .u64 t; cvta.to.shared.u64 t, %1; cvt.u32.u64 %0, t; }" : "=r"(a) : "l"(p));
    return a;
}
__device__ __forceinline__ float to_tf32(float f) {
    uint32_t r;
    asm("cvt.rna.tf32.f32 %0, %1;" : "=r"(r) : "f"(f));
    return __uint_as_float(r);
}
__device__ __forceinline__ void cp16(uint32_t dst, const void* src) {
    asm volatile("cp.async.cg.shared.global [%0], [%1], 16;" :: "r"(dst), "l"(src));
}
#define CP_COMMIT() asm volatile("cp.async.commit_group;" ::: "memory")
#define CP_WAIT0()  asm volatile("cp.async.wait_group 0;" ::: "memory")

// D(16x8,f32) += A(16x8,tf32 row) * B(8x8,tf32 col)
__device__ __forceinline__ void mma8(float* d, const uint32_t* a, const uint32_t* b) {
    asm volatile(
        "mma.sync.aligned.m16n8k8.row.col.f32.tf32.tf32.f32 "
        "{%0,%1,%2,%3}, {%4,%5,%6,%7}, {%8,%9}, {%0,%1,%2,%3};"
        : "+f"(d[0]), "+f"(d[1]), "+f"(d[2]), "+f"(d[3])
        : "r"(a[0]), "r"(a[1]), "r"(a[2]), "r"(a[3]), "r"(b[0]), "r"(b[1]));
}

// ---------------- prepass: permute + tf32-round W2 into g_W2P ----------------
__global__ void w2_permute_kernel(const float* __restrict__ W2) {
    const int idx = blockIdx.x * 256 + threadIdx.x;     // 0 .. F_*E_-1
    const int k = idx >> 9;            // / E_
    const int n = idx & (E_ - 1);

    const int c   = k >> 5;            // chunk
    const int kk  = k & 31;
    const int ks  = kk >> 3;
    const int r8  = kk & 7;
    const int t   = r8 & 3;
    const int rh  = r8 >> 2;           // row half: k offset +0 or +4

    const int n0blk = n >> 8;
    const int n256  = n & 255;
    const int wnb   = n256 >> 6;
    const int n64   = n256 & 63;
    const int g     = n64 & 7;
    const int nt    = n64 >> 3;

    const int f    = rh * 2 + (nt >> 2);
    const int elem = nt & 3;
    const int lane = g * 4 + t;

    const size_t f4idx = (size_t)(((wnb * 4 + ks) * 4 + f) * 32 + lane);
    const size_t dst = ((size_t)c * 2 + n0blk) * BCH_F + f4idx * 4 + elem;
    g_W2P[dst] = to_tf32(W2[(size_t)k * E_ + n]);
}

// ---------------- fused kernel ----------------
// out[m,e] = sum_k relu(b1[k] + sum_q cos(th[q])cos(x[m,q]) W1[q,k]) * W2[k,e] + b2[e]
__global__ __launch_bounds__(NTH, 2)
void ffq_mma_kernel(const float* __restrict__ x,
                    const float* __restrict__ theta,
                    const float* __restrict__ W1,
                    const float* __restrict__ b1,
                    const float* __restrict__ b2,
                    float* __restrict__ out) {
    extern __shared__ float smf[];
    float* hsbuf = smf;                    // [2][BM][PADA]
    float* bbuf  = smf + 2 * HS_F;         // [2][BCH_F]
    const uint32_t sb_b = smem_u32(bbuf);

    const int tid = threadIdx.x;
    const int w   = tid >> 5;
    const int l   = tid & 31;
    const int m0  = blockIdx.x * BM;
    const int n0  = blockIdx.y * BN;

    // warp tile: 2 (m) x 4 (n); WM=32, WN=64
    const int wm  = (w & 1) * 32;
    const int wn  = (w >> 1) * 64;
    const int wnb = w >> 1;

    // h roles
    const int hm = tid & 63;
    const int kq = tid >> 6;

    // fragment lane decomposition
    const int g = l >> 2;
    const int t = l & 3;

    // gmem base for this CTA's permuted B chunks
    const float* w2pc = g_W2P + (size_t)blockIdx.y * BCH_F;   // + c*2*BCH_F per chunk

    // ---- z registers ----
    float zreg[Q_];
    {
        const float4 x0 = *(const float4*)(x + (size_t)(m0 + hm) * E_);
        const float4 x1 = *(const float4*)(x + (size_t)(m0 + hm) * E_ + 4);
        zreg[0] = cosf(theta[0]) * cosf(x0.x);
        zreg[1] = cosf(theta[1]) * cosf(x0.y);
        zreg[2] = cosf(theta[2]) * cosf(x0.z);
        zreg[3] = cosf(theta[3]) * cosf(x0.w);
        zreg[4] = cosf(theta[4]) * cosf(x1.x);
        zreg[5] = cosf(theta[5]) * cosf(x1.y);
        zreg[6] = cosf(theta[6]) * cosf(x1.z);
        zreg[7] = cosf(theta[7]) * cosf(x1.w);
    }

    // ---- prologue: cp.async chunk 0 -> buf0 (linear, coalesced) ----
    {
        const float* src = w2pc;           // c = 0
        #pragma unroll
        for (int i = 0; i < 8; i++)
            cp16(sb_b + (uint32_t)(i * 256 + tid) * 16u,
                 src + (size_t)(i * 256 + tid) * 4);
        CP_COMMIT();
    }
    // ---- compute h(0) -> hs[0] ----
    {
        float* hs0 = hsbuf;
        #pragma unroll
        for (int c2 = 0; c2 < 2; c2++) {
            const int kk = kq * 8 + c2 * 4;
            const float4 b1v = *(const float4*)(b1 + kk);
            float h0 = b1v.x, h1 = b1v.y, h2 = b1v.z, h3 = b1v.w;
            #pragma unroll
            for (int q = 0; q < Q_; q++) {
                const float4 wv = *(const float4*)(W1 + (size_t)q * F_ + kk);
                h0 = fmaf(zreg[q], wv.x, h0);
                h1 = fmaf(zreg[q], wv.y, h1);
                h2 = fmaf(zreg[q], wv.z, h2);
                h3 = fmaf(zreg[q], wv.w, h3);
            }
            float4 o;
            o.x = to_tf32(fmaxf(h0, 0.0f));
            o.y = to_tf32(fmaxf(h1, 0.0f));
            o.z = to_tf32(fmaxf(h2, 0.0f));
            o.w = to_tf32(fmaxf(h3, 0.0f));
            *(float4*)(hs0 + hm * PADA + kk) = o;
        }
    }

    float acc[2][8][4];
    #pragma unroll
    for (int mt = 0; mt < 2; mt++)
        #pragma unroll
        for (int nt = 0; nt < 8; nt++)
            #pragma unroll
            for (int v = 0; v < 4; v++) acc[mt][nt][v] = 0.0f;

    for (int c = 0; c < NCHUNK; c++) {
        const int rb = c & 1;

        CP_WAIT0();
        __syncthreads();     // cp(c) + h(c) visible; prior buffer reads done

        // ---- cp.async chunk c+1 into other B buffer (issue early) ----
        if (c + 1 < NCHUNK) {
            const uint32_t dstb = sb_b + (uint32_t)(rb ^ 1) * (BCH_F * 4u);
            const float* src = w2pc + (size_t)(c + 1) * 2 * BCH_F;
            #pragma unroll
            for (int i = 0; i < 8; i++)
                cp16(dstb + (uint32_t)(i * 256 + tid) * 16u,
                     src + (size_t)(i * 256 + tid) * 4);
            CP_COMMIT();
        }

        // ---- MMA(c) FIRST: tensor pipe fills immediately at barrier release ----
        {
            const float* hsc = hsbuf + rb * HS_F;
            const float4* bch = (const float4*)(bbuf + rb * BCH_F);
            #pragma unroll
            for (int ks = 0; ks < 4; ks++) {
                const int kb = ks * 8;
                // A fragments (scalar LDS, conflict-free via PADA)
                uint32_t a[2][4];
                #pragma unroll
                for (int mt = 0; mt < 2; mt++) {
                    const int r0 = wm + mt * 16 + g;
                    const float* base = hsc + r0 * PADA + kb + t;
                    a[mt][0] = __float_as_uint(base[0]);
                    a[mt][1] = __float_as_uint(base[8 * PADA]);
                    a[mt][2] = __float_as_uint(base[4]);
                    a[mt][3] = __float_as_uint(base[8 * PADA + 4]);
                }
                // B fragments: 4x LDS.128, lane-major -> static names, conflict-free
                const float4* blk = bch + (size_t)((wnb * 4 + ks) * 4) * 32 + l;
                const float4 lg0 = blk[0];        // f=0: rh=0, nt 0..3
                const float4 lg1 = blk[32];       // f=1: rh=0, nt 4..7
                const float4 lg2 = blk[64];       // f=2: rh=1, nt 0..3
                const float4 lg3 = blk[96];       // f=3: rh=1, nt 4..7
                uint32_t bf[8][2];
                bf[0][0] = __float_as_uint(lg0.x); bf[1][0] = __float_as_uint(lg0.y);
                bf[2][0] = __float_as_uint(lg0.z); bf[3][0] = __float_as_uint(lg0.w);
                bf[4][0] = __float_as_uint(lg1.x); bf[5][0] = __float_as_uint(lg1.y);
                bf[6][0] = __float_as_uint(lg1.z); bf[7][0] = __float_as_uint(lg1.w);
                bf[0][1] = __float_as_uint(lg2.x); bf[1][1] = __float_as_uint(lg2.y);
                bf[2][1] = __float_as_uint(lg2.z); bf[3][1] = __float_as_uint(lg2.w);
                bf[4][1] = __float_as_uint(lg3.x); bf[5][1] = __float_as_uint(lg3.y);
                bf[6][1] = __float_as_uint(lg3.z); bf[7][1] = __float_as_uint(lg3.w);

                #pragma unroll
                for (int mt = 0; mt < 2; mt++)
                    #pragma unroll
                    for (int nt = 0; nt < 8; nt++)
                        mma8(acc[mt][nt], a[mt], bf[nt]);
            }
        }

        // ---- h(c+1) AFTER: LDG/FFMA chains trail into barrier slack / cp-wait,
        //      overlapping the other CTA's MMA phase on this SM ----
        if (c + 1 < NCHUNK) {
            const int kc1 = (c + 1) * BK;
            float* hsn = hsbuf + (rb ^ 1) * HS_F;
            #pragma unroll
            for (int c2 = 0; c2 < 2; c2++) {
                const int kk = kq * 8 + c2 * 4;
                const float4 b1v = *(const float4*)(b1 + kc1 + kk);
                float h0 = b1v.x, h1 = b1v.y, h2 = b1v.z, h3 = b1v.w;
                #pragma unroll
                for (int q = 0; q < Q_; q++) {
                    const float4 wv = *(const float4*)(W1 + (size_t)q * F_ + kc1 + kk);
                    h0 = fmaf(zreg[q], wv.x, h0);
                    h1 = fmaf(zreg[q], wv.y, h1);
                    h2 = fmaf(zreg[q], wv.z, h2);
                    h3 = fmaf(zreg[q], wv.w, h3);
                }
                float4 o;
                o.x = to_tf32(fmaxf(h0, 0.0f));
                o.y = to_tf32(fmaxf(h1, 0.0f));
                o.z = to_tf32(fmaxf(h2, 0.0f));
                o.w = to_tf32(fmaxf(h3, 0.0f));
                *(float4*)(hsn + hm * PADA + kk) = o;
            }
        }
    }

    // ---- epilogue: add b2, store ----
    {
        #pragma unroll
        for (int nt = 0; nt < 8; nt++) {
            const int col = n0 + wn + nt * 8 + t * 2;
            const float2 bb = *(const float2*)(b2 + col);
            #pragma unroll
            for (int mt = 0; mt < 2; mt++) {
                const int r0 = m0 + wm + mt * 16 + g;
                float2 v0, v1;
                v0.x = acc[mt][nt][0] + bb.x;
                v0.y = acc[mt][nt][1] + bb.y;
                v1.x = acc[mt][nt][2] + bb.x;
                v1.y = acc[mt][nt][3] + bb.y;
                *(float2*)(out + (size_t)r0 * E_ + col)       = v0;
                *(float2*)(out + (size_t)(r0 + 8) * E_ + col) = v1;
            }
        }
    }
}

extern "C" void kernel_launch(void* const* d_in, const int* in_sizes, int n_in,
                              void* d_out, int out_size) {
    // Identify inputs by element count (order-proof; all sizes distinct)
    const float *x = nullptr, *theta = nullptr, *W1 = nullptr,
                *b1 = nullptr, *W2 = nullptr, *b2 = nullptr;
    for (int i = 0; i < n_in; i++) {
        switch (in_sizes[i]) {
            case B_ * S_ * E_: x     = (const float*)d_in[i]; break;
            case F_ * E_:      W2    = (const float*)d_in[i]; break;
            case Q_ * F_:      W1    = (const float*)d_in[i]; break;
            case F_:           b1    = (const float*)d_in[i]; break;
            case E_:           b2    = (const float*)d_in[i]; break;
            case Q_:           theta = (const float*)d_in[i]; break;
            default: break;
        }
    }
    float* out = (float*)d_out;

    cudaFuncSetAttribute(ffq_mma_kernel,
                         cudaFuncAttributeMaxDynamicSharedMemorySize,
                         SMEM_TOTAL_BYTES);

    // prepass: permute + tf32-round W2 into lane-major fragment order
    w2_permute_kernel<<<(F_ * E_) / 256, 256>>>(W2);

    dim3 grid(M_ / BM, E_ / BN);   // 128 x 2 = 256 CTAs, 2 CTAs/SM
    ffq_mma_kernel<<<grid, NTH, SMEM_TOTAL_BYTES>>>(x, theta, W1, b1, b2, out);
}